// round 16
// baseline (speedup 1.0000x reference)
#include <cuda_runtime.h>
#include <cuda_fp16.h>
#include <math.h>
#include <stdint.h>

#define B_   32
#define F_   40
#define NB_  36
#define R_   512
#define H_   512
#define D_   1536
#define NBF  1280
#define PM   1024
#define M1   46080
#define BFB  1440      // F_*NB_ rows per batch in stage-1

// ---------------- device scratch (static, no allocation) ----------------
__device__ __align__(16) float g_hb [B_*H_];
__device__ __align__(16) float g_hp2[B_*H_];
__device__ __align__(16) float g_e1 [M1];
__device__ __align__(16) float g_p0 [(long)NBF*PM];   // K-split partials
__device__ __align__(16) float g_p1b[(long)NBF*PM];
__device__ __align__(16) float g_p2b[(long)NBF*PM];
__device__ __align__(16) float g_p3b[(long)NBF*PM];
__device__ __align__(16) float g_e2 [B_*F_*F_];
__device__ __align__(16) __half g_Ah [(long)M1*R_];
__device__ __align__(16) __half g_B1h[H_*R_];
__device__ __align__(16) __half g_Fh [(long)NBF*D_];
__device__ __align__(16) __half g_B2h[(long)PM*D_];

// ---------------- portable (non-'a') PTX helpers ----------------
__device__ __forceinline__ uint32_t smem_u32(const void* p){
    uint32_t a;
    asm("{ .reg .u64 t; cvta.to.shared.u64 t, %1; cvt.u32.u64 %0, t; }" : "=r"(a) : "l"(p));
    return a;
}
__device__ __forceinline__ float tanha(float x){
    float y;
    asm("tanh.approx.f32 %0, %1;" : "=f"(y) : "f"(x));
    return y;
}
#define CP_ASYNC16(dst, src) \
    asm volatile("cp.async.cg.shared.global [%0], [%1], 16;" :: "r"(dst), "l"(src) : "memory")
#define CP_COMMIT() asm volatile("cp.async.commit_group;" ::: "memory")
#define CP_WAIT(n)  asm volatile("cp.async.wait_group %0;" :: "n"(n) : "memory")

__device__ __forceinline__ void ldsm4(uint32_t* r, uint32_t addr){
    asm volatile("ldmatrix.sync.aligned.m8n8.x4.shared.b16 {%0,%1,%2,%3}, [%4];"
        : "=r"(r[0]), "=r"(r[1]), "=r"(r[2]), "=r"(r[3]) : "r"(addr));
}
__device__ __forceinline__ void mma16816(float* c, const uint32_t* a, const uint32_t* b){
    asm volatile("mma.sync.aligned.m16n8k16.row.col.f32.f16.f16.f32 "
        "{%0,%1,%2,%3}, {%4,%5,%6,%7}, {%8,%9}, {%0,%1,%2,%3};"
        : "+f"(c[0]), "+f"(c[1]), "+f"(c[2]), "+f"(c[3])
        : "r"(a[0]), "r"(a[1]), "r"(a[2]), "r"(a[3]), "r"(b[0]), "r"(b[1]));
}

__device__ __forceinline__ void hi4_store(float4 v, __half* hi, size_t qi){
    __half2 h01 = __floats2half2_rn(v.x, v.y);
    __half2 h23 = __floats2half2_rn(v.z, v.w);
    reinterpret_cast<uint2*>(hi)[qi] = make_uint2(*(uint32_t*)&h01, *(uint32_t*)&h23);
}

// ============================================================================
// KPREP: one launch: (a) hidden projections, (b) obj->fp16, (c) weights->fp16
// + e1 zeroing, (d) i3d->fp16 straight into g_Fh[:, 512:]. Block-uniform branch.
// ============================================================================
__global__ __launch_bounds__(256) void kprep(
    const float* __restrict__ hidden, const float* __restrict__ Wsh,
    const float* __restrict__ bsh,    const float* __restrict__ bsf,
    const float* __restrict__ Wrh,    const float* __restrict__ brh,
    const float* __restrict__ brf,    const float* __restrict__ obj,
    const float* __restrict__ Wsf,    const float* __restrict__ Wrf,
    const float* __restrict__ i3d)
{
    int blk = blockIdx.x, tid = threadIdx.x;
    if (blk < 512) {
        __shared__ float hs[H_];
        int b = blk >> 4;
        int h = (blk & 15) * 32 + (tid >> 3);
        int ks = tid & 7;
        for (int i = tid; i < H_; i += 256) hs[i] = hidden[b * H_ + i];
        __syncthreads();
        const float4* w1 = reinterpret_cast<const float4*>(Wsh + (long)h * H_) + ks * 16;
        const float4* w2 = reinterpret_cast<const float4*>(Wrh + (long)h * H_) + ks * 16;
        const float*  hk = hs + ks * 64;
        float a1 = 0.f, a2 = 0.f;
        #pragma unroll
        for (int k4 = 0; k4 < 16; k4++) {
            float4 v1 = w1[k4], v2 = w2[k4];
            float h0 = hk[k4*4+0], h1 = hk[k4*4+1], h2 = hk[k4*4+2], h3 = hk[k4*4+3];
            a1 = fmaf(h0, v1.x, a1); a1 = fmaf(h1, v1.y, a1);
            a1 = fmaf(h2, v1.z, a1); a1 = fmaf(h3, v1.w, a1);
            a2 = fmaf(h0, v2.x, a2); a2 = fmaf(h1, v2.y, a2);
            a2 = fmaf(h2, v2.z, a2); a2 = fmaf(h3, v2.w, a2);
        }
        #pragma unroll
        for (int off = 4; off; off >>= 1) {
            a1 += __shfl_xor_sync(0xffffffffu, a1, off);
            a2 += __shfl_xor_sync(0xffffffffu, a2, off);
        }
        if (ks == 0) {
            g_hb [b * H_ + h] = a1 + bsh[h] + bsf[h];
            g_hp2[b * H_ + h] = a2 + brh[h] + brf[h];
        }
    } else if (blk < 23552) {
        size_t i = (size_t)(blk - 512) * 256 + tid;
        float4 v = reinterpret_cast<const float4*>(obj)[i];
        hi4_store(v, g_Ah, i);
    } else if (blk < 25344) {
        size_t q = (size_t)(blk - 23552) * 256 + tid;
        if (q < M1) g_e1[q] = 0.f;
        if (q < 65536) {                                 // B1: Wsf 512x512
            float4 v = reinterpret_cast<const float4*>(Wsf)[q];
            hi4_store(v, g_B1h, q);
        } else {                                         // B2: rearranged Wrf -> 1024x1536
            size_t j = q - 65536;
            int m = (int)(j / 384), c4 = (int)(j % 384);
            const float* row = Wrf + (long)(m & 511) * (2 * D_) + (m >> 9) * D_;
            float4 v = reinterpret_cast<const float4*>(row)[c4];
            hi4_store(v, g_B2h, (size_t)m * (D_ / 4) + c4);
        }
    } else {                                             // i3d -> Fh[:, 512:]
        size_t q = (size_t)(blk - 25344) * 256 + tid;    // [0, 327680)
        int bf = (int)(q >> 8), w = (int)(q & 255);
        float4 v = reinterpret_cast<const float4*>(i3d)[q];
        hi4_store(v, g_Fh, (size_t)bf * (D_ / 4) + 128 + w);
    }
}

// ============================================================================
// KMMA: NST-stage cp.async + ldmatrix + mma.sync fp16 GEMM, one __syncthreads
// per K-chunk (Kc=64, SW128 swizzle). CTA tile MT x NT, 8 warps, 2 CTAs/SM.
// MODE 1: tanh.approx reduce -> atomicAdd g_e1 (N-split via blockIdx.y).
// MODE 2: K-chunks [KOFF0 + z*NC, +NC) -> partial buffer (PBASE + z).
// ============================================================================
template<int MT, int NT, int NST> struct KCfg {
    static constexpr int STAGE = (MT + NT) * 128;
    static constexpr int SBUF  = NST * STAGE;
    static constexpr int TOT   = SBUF + 3 * NT * 4;
};

template<int KD, int NC, int MODE, int MT, int NT, int NST, int KOFF0, int PBASE>
__global__ __launch_bounds__(256, 2)
void kmma(const float* __restrict__ wasp)
{
    constexpr int STAGE = KCfg<MT, NT, NST>::STAGE;
    constexpr int SBUF  = KCfg<MT, NT, NST>::SBUF;
    constexpr int NW    = NT / 2;        // cols per warp
    constexpr int MI    = MT / 64;       // 16-row sub-tiles per warp
    extern __shared__ char smem[];
    const uint32_t sb = smem_u32(smem);
    const int tid  = threadIdx.x, lane = tid & 31, wid = tid >> 5;
    const int wm   = wid & 3, wn = wid >> 2;
    const int row0 = blockIdx.x * MT;
    const int n0c  = blockIdx.y * NT;
    const int koff = KOFF0 + blockIdx.z * NC;

    const __half *Ah, *Bh;
    if (MODE == 1) { Ah = g_Ah; Bh = g_B1h; }
    else           { Ah = g_Fh; Bh = g_B2h; }

    float* was_s = (float*)(smem + SBUF);
    float* hb_s  = (float*)(smem + SBUF + NT * 4);
    int b0 = 0;
    if (MODE == 1) {
        b0 = row0 / BFB;
        int b1 = (row0 + MT - 1) / BFB;
        for (int i = tid; i < NT; i += 256) {
            was_s[i]      = wasp[n0c + i];
            hb_s[i]       = g_hb[b0 * H_ + n0c + i];
            hb_s[NT + i]  = g_hb[b1 * H_ + n0c + i];
        }
    }

    const int ldr = tid >> 3;            // base row (+32 per iter)
    const int ldq = tid & 7;             // 16B chunk within 128B row

    const int sub = lane >> 3, lr = lane & 7;
    const int a_row = wm * (16 * MI) + ((sub & 1) << 3) + lr;
    const int a_cb  = (sub >> 1) << 4;
    const int b_row = wn * NW + ((sub >> 1) << 3) + lr;
    const int b_cb  = (sub & 1) << 4;
    const uint32_t amask = (uint32_t)((a_row & 7) << 4);
    const uint32_t bmask = (uint32_t)((b_row & 7) << 4);

    float acc[MI][NW / 8][4];
    #pragma unroll
    for (int i = 0; i < MI; i++)
        #pragma unroll
        for (int j = 0; j < NW / 8; j++)
            #pragma unroll
            for (int v = 0; v < 4; v++) acc[i][j][v] = 0.f;

    auto load_chunk = [&](int c) {
        const long kin = (long)(c + koff) * 64;
        uint32_t abase = sb + (uint32_t)(c % NST) * STAGE;
        uint32_t bbase = abase + MT * 128;
        #pragma unroll
        for (int it = 0; it < MT / 32; it++) {
            int r = ldr + it * 32;
            uint32_t off = (uint32_t)(r * 128 + ldq * 16) ^ ((uint32_t)(r & 7) << 4);
            CP_ASYNC16(abase + off, Ah + (long)(row0 + r) * KD + kin + ldq * 8);
        }
        #pragma unroll
        for (int it = 0; it < NT / 32; it++) {
            int r = ldr + it * 32;
            uint32_t off = (uint32_t)(r * 128 + ldq * 16) ^ ((uint32_t)(r & 7) << 4);
            CP_ASYNC16(bbase + off, Bh + (long)(n0c + r) * KD + kin + ldq * 8);
        }
        CP_COMMIT();
    };

    auto compute_chunk = [&](int c) {
        uint32_t abase = sb + (uint32_t)(c % NST) * STAGE;
        uint32_t bbase = abase + MT * 128;
        #pragma unroll
        for (int ks = 0; ks < 4; ks++) {
            const uint32_t kb = (uint32_t)(ks * 32);
            uint32_t af[MI][4], bfr[NW / 16][4];
            #pragma unroll
            for (int i = 0; i < MI; i++)
                ldsm4(af[i], abase + (uint32_t)((a_row + i * 16) * 128)
                                   + (((uint32_t)a_cb + kb) ^ amask));
            #pragma unroll
            for (int j2 = 0; j2 < NW / 16; j2++)
                ldsm4(bfr[j2], bbase + (uint32_t)((b_row + j2 * 16) * 128)
                                     + (((uint32_t)b_cb + kb) ^ bmask));
            #pragma unroll
            for (int i = 0; i < MI; i++)
                #pragma unroll
                for (int j = 0; j < NW / 8; j++)
                    mma16816(acc[i][j], af[i], &bfr[j >> 1][(j & 1) * 2]);
        }
    };

    #pragma unroll
    for (int c = 0; c < NST - 1; c++) load_chunk(c);
    for (int c = 0; c < NC; c++) {
        CP_WAIT(NST - 2);
        __syncthreads();
        compute_chunk(c);
        if (c + NST - 1 < NC) load_chunk(c + NST - 1); else CP_COMMIT();
    }

    const int g = lane >> 2, t = lane & 3;
    if (MODE == 1) {
        #pragma unroll
        for (int i = 0; i < MI; i++) {
            int rl = wm * (16 * MI) + i * 16 + g;
            int rh = rl + 8;
            const float* hbl = hb_s + (((row0 + rl) / BFB) == b0 ? 0 : NT);
            const float* hbh = hb_s + (((row0 + rh) / BFB) == b0 ? 0 : NT);
            float pl = 0.f, ph = 0.f;
            #pragma unroll
            for (int j = 0; j < NW / 8; j++) {
                int nl = wn * NW + j * 8 + 2 * t;
                float w0 = was_s[nl], w1 = was_s[nl + 1];
                pl += w0 * tanha(acc[i][j][0] + hbl[nl])
                    + w1 * tanha(acc[i][j][1] + hbl[nl + 1]);
                ph += w0 * tanha(acc[i][j][2] + hbh[nl])
                    + w1 * tanha(acc[i][j][3] + hbh[nl + 1]);
            }
            pl += __shfl_xor_sync(0xffffffffu, pl, 1);
            pl += __shfl_xor_sync(0xffffffffu, pl, 2);
            ph += __shfl_xor_sync(0xffffffffu, ph, 1);
            ph += __shfl_xor_sync(0xffffffffu, ph, 2);
            if (t == 0) {
                atomicAdd(&g_e1[row0 + rl], pl);
                atomicAdd(&g_e1[row0 + rh], ph);
            }
        }
    } else {
        int pz = PBASE + blockIdx.z;
        float* outp = (pz == 0) ? g_p0 : (pz == 1) ? g_p1b
                    : (pz == 2) ? g_p2b : g_p3b;
        #pragma unroll
        for (int i = 0; i < MI; i++) {
            int rl = row0 + wm * (16 * MI) + i * 16 + g;
            #pragma unroll
            for (int j = 0; j < NW / 8; j++) {
                int nc = n0c + wn * NW + j * 8 + 2 * t;
                *reinterpret_cast<float2*>(&outp[(long)rl * PM + nc])
                    = make_float2(acc[i][j][0], acc[i][j][1]);
                *reinterpret_cast<float2*>(&outp[(long)(rl + 8) * PM + nc])
                    = make_float2(acc[i][j][2], acc[i][j][3]);
            }
        }
    }
}

// ============================================================================
// K3: softmax over NB + attention, VECTORIZED: block=64, each thread owns
// 8 contiguous d's (uint4 per l-row), fp32 accumulation -> fp16 feat[:, :512]
// ============================================================================
__global__ __launch_bounds__(64) void k3_soft()
{
    __shared__ float alpha[NB_];
    int bf = blockIdx.x, tid = threadIdx.x;
    const __half* fb = g_Ah + (long)bf * NB_ * R_;
    if (tid == 0) {
        float e_s[NB_];
        float m = -1e30f;
        #pragma unroll
        for (int l = 0; l < NB_; l++) { e_s[l] = g_e1[bf * NB_ + l]; m = fmaxf(m, e_s[l]); }
        float s = 0.f;
        #pragma unroll
        for (int l = 0; l < NB_; l++) { e_s[l] = expf(e_s[l] - m); s += e_s[l]; }
        float inv = 1.f / s;
        #pragma unroll
        for (int l = 0; l < NB_; l++) alpha[l] = e_s[l] * inv;
    }
    __syncthreads();

    const uint4* fbv = reinterpret_cast<const uint4*>(fb) + tid;   // 8 halves per row
    float acc[8] = {0.f, 0.f, 0.f, 0.f, 0.f, 0.f, 0.f, 0.f};
    #pragma unroll 6
    for (int l = 0; l < NB_; l++) {
        uint4 v = fbv[l * (R_ / 8)];
        float a = alpha[l];
        float2 p0 = __half22float2(*reinterpret_cast<__half2*>(&v.x));
        float2 p1 = __half22float2(*reinterpret_cast<__half2*>(&v.y));
        float2 p2 = __half22float2(*reinterpret_cast<__half2*>(&v.z));
        float2 p3 = __half22float2(*reinterpret_cast<__half2*>(&v.w));
        acc[0] = fmaf(a, p0.x, acc[0]); acc[1] = fmaf(a, p0.y, acc[1]);
        acc[2] = fmaf(a, p1.x, acc[2]); acc[3] = fmaf(a, p1.y, acc[3]);
        acc[4] = fmaf(a, p2.x, acc[4]); acc[5] = fmaf(a, p2.y, acc[5]);
        acc[6] = fmaf(a, p3.x, acc[6]); acc[7] = fmaf(a, p3.y, acc[7]);
    }
    uint4 o;
    __half2 h0 = __floats2half2_rn(acc[0], acc[1]);
    __half2 h1 = __floats2half2_rn(acc[2], acc[3]);
    __half2 h2 = __floats2half2_rn(acc[4], acc[5]);
    __half2 h3 = __floats2half2_rn(acc[6], acc[7]);
    o.x = *reinterpret_cast<uint32_t*>(&h0);
    o.y = *reinterpret_cast<uint32_t*>(&h1);
    o.z = *reinterpret_cast<uint32_t*>(&h2);
    o.w = *reinterpret_cast<uint32_t*>(&h3);
    reinterpret_cast<uint4*>(g_Fh + (long)bf * D_)[tid] = o;
}

// ============================================================================
// K5: e2[b,i,j] = war . tanh(p2[b,i] + p1[b,j] + hp2[b]); p = sum of 4
// K-split partials. grid (32,5)
// ============================================================================
__global__ __launch_bounds__(256) void k5_e2(const float* __restrict__ war)
{
    __shared__ float base[8][H_];
    __shared__ float warr[H_];
    int b = blockIdx.x, i0 = blockIdx.y * 8;
    int tid = threadIdx.x, warp = tid >> 5, lane = tid & 31;
    for (int h = tid; h < H_; h += 256) warr[h] = war[h];
    for (int idx = tid; idx < 8 * H_; idx += 256) {
        int ii = idx >> 9, h = idx & (H_ - 1);
        long o = (long)(b * F_ + i0 + ii) * PM + H_ + h;
        base[ii][h] = (g_p0[o] + g_p1b[o]) + (g_p2b[o] + g_p3b[o])
                    + g_hp2[b * H_ + h];
    }
    __syncthreads();
    for (int jj = 0; jj < 5; jj++) {
        int j = jj * 8 + warp;
        long rowo = (long)(b * F_ + j) * PM;
        float p1v[16];
        #pragma unroll
        for (int kk = 0; kk < 16; kk++) {
            long o = rowo + lane + kk * 32;
            p1v[kk] = (g_p0[o] + g_p1b[o]) + (g_p2b[o] + g_p3b[o]);
        }
        #pragma unroll
        for (int ii = 0; ii < 8; ii++) {
            float part = 0.f;
            #pragma unroll
            for (int kk = 0; kk < 16; kk++) {
                int h = lane + kk * 32;
                part += warr[h] * tanha(base[ii][h] + p1v[kk]);
            }
            #pragma unroll
            for (int off = 16; off; off >>= 1)
                part += __shfl_xor_sync(0xffffffffu, part, off);
            if (lane == 0) g_e2[(long)b * (F_ * F_) + (i0 + ii) * F_ + j] = part;
        }
    }
}

// ============================================================================
// K6: per-batch softmax over F*F, marginals, weighted sums from fp16 feat.
// grid (32,3).
// ============================================================================
__global__ __launch_bounds__(256) void k6_final(float* __restrict__ out)
{
    __shared__ float ex[F_ * F_];
    __shared__ float red[256];
    __shared__ float rowsum[F_], colsum[F_];
    int b = blockIdx.x, tid = threadIdx.x;
    const float* e = g_e2 + b * (F_ * F_);

    float m = -1e30f;
    for (int t = tid; t < F_ * F_; t += 256) m = fmaxf(m, e[t]);
    red[tid] = m; __syncthreads();
    for (int s = 128; s > 0; s >>= 1) {
        if (tid < s) red[tid] = fmaxf(red[tid], red[tid + s]);
        __syncthreads();
    }
    m = red[0]; __syncthreads();

    float sum = 0.f;
    for (int t = tid; t < F_ * F_; t += 256) { float v = expf(e[t] - m); ex[t] = v; sum += v; }
    red[tid] = sum; __syncthreads();
    for (int s = 128; s > 0; s >>= 1) {
        if (tid < s) red[tid] += red[tid + s];
        __syncthreads();
    }
    float inv = 1.f / red[0];

    if (tid < F_) { rowsum[tid] = 0.f; colsum[tid] = 0.f; }
    __syncthreads();
    for (int t = tid; t < F_ * F_; t += 256) {
        float a = ex[t] * inv;
        atomicAdd(&rowsum[t / F_], a);
        atomicAdd(&colsum[t % F_], a);
    }
    __syncthreads();

    int c0 = blockIdx.y * 512;
    for (int d = c0 + tid; d < c0 + 512; d += 256) {
        float r1 = 0.f, r2 = 0.f;
        #pragma unroll 8
        for (int q = 0; q < F_; q++) {
            float fv = __half2float(g_Fh[(long)(b * F_ + q) * D_ + d]);
            r1 = fmaf(colsum[q], fv, r1);
            r2 = fmaf(rowsum[q], fv, r2);
        }
        out[b * (2 * D_) + d]      = r1;
        out[b * (2 * D_) + D_ + d] = r2;
    }
}

// ============================================================================
extern "C" void kernel_launch(void* const* d_in, const int* in_sizes, int n_in,
                              void* d_out, int out_size)
{
    const float* i3d    = (const float*)d_in[0];
    const float* obj    = (const float*)d_in[1];
    const float* hidden = (const float*)d_in[2];
    const float* Wsf    = (const float*)d_in[3];
    const float* bsf    = (const float*)d_in[4];
    const float* Wsh    = (const float*)d_in[5];
    const float* bsh    = (const float*)d_in[6];
    const float* was    = (const float*)d_in[7];
    const float* Wrf    = (const float*)d_in[8];
    const float* brf    = (const float*)d_in[9];
    const float* Wrh    = (const float*)d_in[10];
    const float* brh    = (const float*)d_in[11];
    const float* war    = (const float*)d_in[12];
    float* out = (float*)d_out;

    static cudaStream_t s2 = nullptr;
    static cudaEvent_t ev1 = nullptr, ev2 = nullptr;
    if (s2 == nullptr) {
        cudaStreamCreateWithFlags(&s2, cudaStreamNonBlocking);
        cudaEventCreateWithFlags(&ev1, cudaEventDisableTiming);
        cudaEventCreateWithFlags(&ev2, cudaEventDisableTiming);
    }

    // kmma1: stage-1. kmma2b: i3d part of p (K-chunks 8..23, partials 0/1).
    // kmma2a: obj_att part of p (K-chunks 0..7, partials 2/3).
    auto km1  = kmma<512, 8, 1, 128, 128, 3, 0, 0>;
    auto km2b = kmma<1536, 8, 2, 128, 128, 3, 8, 0>;
    auto km2a = kmma<1536, 4, 2, 128, 128, 3, 0, 2>;
    cudaFuncSetAttribute((const void*)km1,
        cudaFuncAttributeMaxDynamicSharedMemorySize, KCfg<128, 128, 3>::TOT);
    cudaFuncSetAttribute((const void*)km2b,
        cudaFuncAttributeMaxDynamicSharedMemorySize, KCfg<128, 128, 3>::TOT);
    cudaFuncSetAttribute((const void*)km2a,
        cudaFuncAttributeMaxDynamicSharedMemorySize, KCfg<128, 128, 3>::TOT);

    kprep <<<26624, 256>>>(hidden, Wsh, bsh, bsf, Wrh, brh, brf, obj, Wsf, Wrf, i3d);

    // Fork: i3d GEMM runs on s2 concurrently with stage-1 on the main stream.
    cudaEventRecord(ev1, 0);
    cudaStreamWaitEvent(s2, ev1, 0);
    km2b <<<dim3(NBF / 128, 8, 2), 256, KCfg<128, 128, 3>::TOT, s2>>>(nullptr);
    cudaEventRecord(ev2, s2);

    km1 <<<dim3(M1 / 128, 4), 256, KCfg<128, 128, 3>::TOT>>>(was);
    k3_soft <<<NBF, 64>>>();
    km2a <<<dim3(NBF / 128, 8, 2), 256, KCfg<128, 128, 3>::TOT>>>(nullptr);

    // Join: k5 needs all four partial buffers.
    cudaStreamWaitEvent(0, ev2, 0);
    k5_e2   <<<dim3(B_, 5), 256>>>(war);
    k6_final<<<dim3(B_, 3), 256>>>(out);
}

// round 17
// speedup vs baseline: 1.4805x; 1.4805x over previous
#include <cuda_runtime.h>
#include <cuda_fp16.h>
#include <math.h>
#include <stdint.h>

#define B_   32
#define F_   40
#define NB_  36
#define R_   512
#define H_   512
#define D_   1536
#define NBF  1280
#define PM   1024
#define M1   46080
#define BFB  1440      // F_*NB_ rows per batch in stage-1

// ---------------- device scratch (static, no allocation) ----------------
__device__ __align__(16) float g_hb [B_*H_];
__device__ __align__(16) float g_hp2[B_*H_];
__device__ __align__(16) float g_e1 [M1];
__device__ __align__(16) float g_p0 [(long)NBF*PM];   // K-split partials
__device__ __align__(16) float g_p1b[(long)NBF*PM];
__device__ __align__(16) float g_p2b[(long)NBF*PM];
__device__ __align__(16) float g_p3b[(long)NBF*PM];
__device__ __align__(16) float g_e2 [B_*F_*F_];
__device__ __align__(16) __half g_Ah [(long)M1*R_];
__device__ __align__(16) __half g_B1h[H_*R_];
__device__ __align__(16) __half g_Fh [(long)NBF*D_];
__device__ __align__(16) __half g_B2h[(long)PM*D_];

// ---------------- portable (non-'a') PTX helpers ----------------
__device__ __forceinline__ uint32_t smem_u32(const void* p){
    uint32_t a;
    asm("{ .reg .u64 t; cvta.to.shared.u64 t, %1; cvt.u32.u64 %0, t; }" : "=r"(a) : "l"(p));
    return a;
}
__device__ __forceinline__ float tanha(float x){
    float y;
    asm("tanh.approx.f32 %0, %1;" : "=f"(y) : "f"(x));
    return y;
}
#define CP_ASYNC16(dst, src) \
    asm volatile("cp.async.cg.shared.global [%0], [%1], 16;" :: "r"(dst), "l"(src) : "memory")
#define CP_COMMIT() asm volatile("cp.async.commit_group;" ::: "memory")
#define CP_WAIT(n)  asm volatile("cp.async.wait_group %0;" :: "n"(n) : "memory")

__device__ __forceinline__ void ldsm4(uint32_t* r, uint32_t addr){
    asm volatile("ldmatrix.sync.aligned.m8n8.x4.shared.b16 {%0,%1,%2,%3}, [%4];"
        : "=r"(r[0]), "=r"(r[1]), "=r"(r[2]), "=r"(r[3]) : "r"(addr));
}
__device__ __forceinline__ void mma16816(float* c, const uint32_t* a, const uint32_t* b){
    asm volatile("mma.sync.aligned.m16n8k16.row.col.f32.f16.f16.f32 "
        "{%0,%1,%2,%3}, {%4,%5,%6,%7}, {%8,%9}, {%0,%1,%2,%3};"
        : "+f"(c[0]), "+f"(c[1]), "+f"(c[2]), "+f"(c[3])
        : "r"(a[0]), "r"(a[1]), "r"(a[2]), "r"(a[3]), "r"(b[0]), "r"(b[1]));
}

__device__ __forceinline__ void hi4_store(float4 v, __half* hi, size_t qi){
    __half2 h01 = __floats2half2_rn(v.x, v.y);
    __half2 h23 = __floats2half2_rn(v.z, v.w);
    reinterpret_cast<uint2*>(hi)[qi] = make_uint2(*(uint32_t*)&h01, *(uint32_t*)&h23);
}

// ============================================================================
// KPREP: one launch: (a) hidden projections, (b) obj->fp16, (c) weights->fp16
// + e1 zeroing, (d) i3d->fp16 straight into g_Fh[:, 512:]. Block-uniform branch.
// ============================================================================
__global__ __launch_bounds__(256) void kprep(
    const float* __restrict__ hidden, const float* __restrict__ Wsh,
    const float* __restrict__ bsh,    const float* __restrict__ bsf,
    const float* __restrict__ Wrh,    const float* __restrict__ brh,
    const float* __restrict__ brf,    const float* __restrict__ obj,
    const float* __restrict__ Wsf,    const float* __restrict__ Wrf,
    const float* __restrict__ i3d)
{
    int blk = blockIdx.x, tid = threadIdx.x;
    if (blk < 512) {
        __shared__ float hs[H_];
        int b = blk >> 4;
        int h = (blk & 15) * 32 + (tid >> 3);
        int ks = tid & 7;
        for (int i = tid; i < H_; i += 256) hs[i] = hidden[b * H_ + i];
        __syncthreads();
        const float4* w1 = reinterpret_cast<const float4*>(Wsh + (long)h * H_) + ks * 16;
        const float4* w2 = reinterpret_cast<const float4*>(Wrh + (long)h * H_) + ks * 16;
        const float*  hk = hs + ks * 64;
        float a1 = 0.f, a2 = 0.f;
        #pragma unroll
        for (int k4 = 0; k4 < 16; k4++) {
            float4 v1 = w1[k4], v2 = w2[k4];
            float h0 = hk[k4*4+0], h1 = hk[k4*4+1], h2 = hk[k4*4+2], h3 = hk[k4*4+3];
            a1 = fmaf(h0, v1.x, a1); a1 = fmaf(h1, v1.y, a1);
            a1 = fmaf(h2, v1.z, a1); a1 = fmaf(h3, v1.w, a1);
            a2 = fmaf(h0, v2.x, a2); a2 = fmaf(h1, v2.y, a2);
            a2 = fmaf(h2, v2.z, a2); a2 = fmaf(h3, v2.w, a2);
        }
        #pragma unroll
        for (int off = 4; off; off >>= 1) {
            a1 += __shfl_xor_sync(0xffffffffu, a1, off);
            a2 += __shfl_xor_sync(0xffffffffu, a2, off);
        }
        if (ks == 0) {
            g_hb [b * H_ + h] = a1 + bsh[h] + bsf[h];
            g_hp2[b * H_ + h] = a2 + brh[h] + brf[h];
        }
    } else if (blk < 23552) {
        size_t i = (size_t)(blk - 512) * 256 + tid;
        float4 v = reinterpret_cast<const float4*>(obj)[i];
        hi4_store(v, g_Ah, i);
    } else if (blk < 25344) {
        size_t q = (size_t)(blk - 23552) * 256 + tid;
        if (q < M1) g_e1[q] = 0.f;
        if (q < 65536) {                                 // B1: Wsf 512x512
            float4 v = reinterpret_cast<const float4*>(Wsf)[q];
            hi4_store(v, g_B1h, q);
        } else {                                         // B2: rearranged Wrf -> 1024x1536
            size_t j = q - 65536;
            int m = (int)(j / 384), c4 = (int)(j % 384);
            const float* row = Wrf + (long)(m & 511) * (2 * D_) + (m >> 9) * D_;
            float4 v = reinterpret_cast<const float4*>(row)[c4];
            hi4_store(v, g_B2h, (size_t)m * (D_ / 4) + c4);
        }
    } else {                                             // i3d -> Fh[:, 512:]
        size_t q = (size_t)(blk - 25344) * 256 + tid;    // [0, 327680)
        int bf = (int)(q >> 8), w = (int)(q & 255);
        float4 v = reinterpret_cast<const float4*>(i3d)[q];
        hi4_store(v, g_Fh, (size_t)bf * (D_ / 4) + 128 + w);
    }
}

// ============================================================================
// KMMA: NST-stage cp.async + ldmatrix + mma.sync fp16 GEMM, one __syncthreads
// per K-chunk (Kc=64, SW128 swizzle). CTA tile MT x NT, 8 warps, 2 CTAs/SM.
// MODE 1: tanh.approx reduce -> atomicAdd g_e1 (N-split via blockIdx.y).
// MODE 2: K-chunks [KOFF0 + z*NC, +NC) -> partial buffer (PBASE + z).
// ============================================================================
template<int MT, int NT, int NST> struct KCfg {
    static constexpr int STAGE = (MT + NT) * 128;
    static constexpr int SBUF  = NST * STAGE;
    static constexpr int TOT   = SBUF + 3 * NT * 4;
};

template<int KD, int NC, int MODE, int MT, int NT, int NST, int KOFF0, int PBASE>
__global__ __launch_bounds__(256, 2)
void kmma(const float* __restrict__ wasp)
{
    constexpr int STAGE = KCfg<MT, NT, NST>::STAGE;
    constexpr int SBUF  = KCfg<MT, NT, NST>::SBUF;
    constexpr int NW    = NT / 2;        // cols per warp
    constexpr int MI    = MT / 64;       // 16-row sub-tiles per warp
    extern __shared__ char smem[];
    const uint32_t sb = smem_u32(smem);
    const int tid  = threadIdx.x, lane = tid & 31, wid = tid >> 5;
    const int wm   = wid & 3, wn = wid >> 2;
    const int row0 = blockIdx.x * MT;
    const int n0c  = blockIdx.y * NT;
    const int koff = KOFF0 + blockIdx.z * NC;

    const __half *Ah, *Bh;
    if (MODE == 1) { Ah = g_Ah; Bh = g_B1h; }
    else           { Ah = g_Fh; Bh = g_B2h; }

    float* was_s = (float*)(smem + SBUF);
    float* hb_s  = (float*)(smem + SBUF + NT * 4);
    int b0 = 0;
    if (MODE == 1) {
        b0 = row0 / BFB;
        int b1 = (row0 + MT - 1) / BFB;
        for (int i = tid; i < NT; i += 256) {
            was_s[i]      = wasp[n0c + i];
            hb_s[i]       = g_hb[b0 * H_ + n0c + i];
            hb_s[NT + i]  = g_hb[b1 * H_ + n0c + i];
        }
    }

    const int ldr = tid >> 3;            // base row (+32 per iter)
    const int ldq = tid & 7;             // 16B chunk within 128B row

    const int sub = lane >> 3, lr = lane & 7;
    const int a_row = wm * (16 * MI) + ((sub & 1) << 3) + lr;
    const int a_cb  = (sub >> 1) << 4;
    const int b_row = wn * NW + ((sub >> 1) << 3) + lr;
    const int b_cb  = (sub & 1) << 4;
    const uint32_t amask = (uint32_t)((a_row & 7) << 4);
    const uint32_t bmask = (uint32_t)((b_row & 7) << 4);

    float acc[MI][NW / 8][4];
    #pragma unroll
    for (int i = 0; i < MI; i++)
        #pragma unroll
        for (int j = 0; j < NW / 8; j++)
            #pragma unroll
            for (int v = 0; v < 4; v++) acc[i][j][v] = 0.f;

    auto load_chunk = [&](int c) {
        const long kin = (long)(c + koff) * 64;
        uint32_t abase = sb + (uint32_t)(c % NST) * STAGE;
        uint32_t bbase = abase + MT * 128;
        #pragma unroll
        for (int it = 0; it < MT / 32; it++) {
            int r = ldr + it * 32;
            uint32_t off = (uint32_t)(r * 128 + ldq * 16) ^ ((uint32_t)(r & 7) << 4);
            CP_ASYNC16(abase + off, Ah + (long)(row0 + r) * KD + kin + ldq * 8);
        }
        #pragma unroll
        for (int it = 0; it < NT / 32; it++) {
            int r = ldr + it * 32;
            uint32_t off = (uint32_t)(r * 128 + ldq * 16) ^ ((uint32_t)(r & 7) << 4);
            CP_ASYNC16(bbase + off, Bh + (long)(n0c + r) * KD + kin + ldq * 8);
        }
        CP_COMMIT();
    };

    auto compute_chunk = [&](int c) {
        uint32_t abase = sb + (uint32_t)(c % NST) * STAGE;
        uint32_t bbase = abase + MT * 128;
        #pragma unroll
        for (int ks = 0; ks < 4; ks++) {
            const uint32_t kb = (uint32_t)(ks * 32);
            uint32_t af[MI][4], bfr[NW / 16][4];
            #pragma unroll
            for (int i = 0; i < MI; i++)
                ldsm4(af[i], abase + (uint32_t)((a_row + i * 16) * 128)
                                   + (((uint32_t)a_cb + kb) ^ amask));
            #pragma unroll
            for (int j2 = 0; j2 < NW / 16; j2++)
                ldsm4(bfr[j2], bbase + (uint32_t)((b_row + j2 * 16) * 128)
                                     + (((uint32_t)b_cb + kb) ^ bmask));
            #pragma unroll
            for (int i = 0; i < MI; i++)
                #pragma unroll
                for (int j = 0; j < NW / 8; j++)
                    mma16816(acc[i][j], af[i], &bfr[j >> 1][(j & 1) * 2]);
        }
    };

    #pragma unroll
    for (int c = 0; c < NST - 1; c++) load_chunk(c);
    for (int c = 0; c < NC; c++) {
        CP_WAIT(NST - 2);
        __syncthreads();
        compute_chunk(c);
        if (c + NST - 1 < NC) load_chunk(c + NST - 1); else CP_COMMIT();
    }

    const int g = lane >> 2, t = lane & 3;
    if (MODE == 1) {
        #pragma unroll
        for (int i = 0; i < MI; i++) {
            int rl = wm * (16 * MI) + i * 16 + g;
            int rh = rl + 8;
            const float* hbl = hb_s + (((row0 + rl) / BFB) == b0 ? 0 : NT);
            const float* hbh = hb_s + (((row0 + rh) / BFB) == b0 ? 0 : NT);
            float pl = 0.f, ph = 0.f;
            #pragma unroll
            for (int j = 0; j < NW / 8; j++) {
                int nl = wn * NW + j * 8 + 2 * t;
                float w0 = was_s[nl], w1 = was_s[nl + 1];
                pl += w0 * tanha(acc[i][j][0] + hbl[nl])
                    + w1 * tanha(acc[i][j][1] + hbl[nl + 1]);
                ph += w0 * tanha(acc[i][j][2] + hbh[nl])
                    + w1 * tanha(acc[i][j][3] + hbh[nl + 1]);
            }
            pl += __shfl_xor_sync(0xffffffffu, pl, 1);
            pl += __shfl_xor_sync(0xffffffffu, pl, 2);
            ph += __shfl_xor_sync(0xffffffffu, ph, 1);
            ph += __shfl_xor_sync(0xffffffffu, ph, 2);
            if (t == 0) {
                atomicAdd(&g_e1[row0 + rl], pl);
                atomicAdd(&g_e1[row0 + rh], ph);
            }
        }
    } else {
        int pz = PBASE + blockIdx.z;
        float* outp = (pz == 0) ? g_p0 : (pz == 1) ? g_p1b
                    : (pz == 2) ? g_p2b : g_p3b;
        #pragma unroll
        for (int i = 0; i < MI; i++) {
            int rl = row0 + wm * (16 * MI) + i * 16 + g;
            #pragma unroll
            for (int j = 0; j < NW / 8; j++) {
                int nc = n0c + wn * NW + j * 8 + 2 * t;
                *reinterpret_cast<float2*>(&outp[(long)rl * PM + nc])
                    = make_float2(acc[i][j][0], acc[i][j][1]);
                *reinterpret_cast<float2*>(&outp[(long)(rl + 8) * PM + nc])
                    = make_float2(acc[i][j][2], acc[i][j][3]);
            }
        }
    }
}

// ============================================================================
// K3: softmax over NB + attention, vectorized, block=256 covering 4 bf-rows
// (64 threads each; each thread owns 8 contiguous d's as one uint4 per l-row).
// grid = NBF/4.
// ============================================================================
__global__ __launch_bounds__(256) void k3_soft()
{
    __shared__ float alpha[4][NB_];
    int tid = threadIdx.x;
    int s   = tid >> 6;                 // sub-block 0..3
    int t   = tid & 63;                 // lane within sub-block
    int bf  = blockIdx.x * 4 + s;

    if (t == 0) {
        float e_s[NB_];
        float m = -1e30f;
        #pragma unroll
        for (int l = 0; l < NB_; l++) { e_s[l] = g_e1[bf * NB_ + l]; m = fmaxf(m, e_s[l]); }
        float sm = 0.f;
        #pragma unroll
        for (int l = 0; l < NB_; l++) { e_s[l] = expf(e_s[l] - m); sm += e_s[l]; }
        float inv = 1.f / sm;
        #pragma unroll
        for (int l = 0; l < NB_; l++) alpha[s][l] = e_s[l] * inv;
    }
    __syncthreads();

    const uint4* fbv = reinterpret_cast<const uint4*>(g_Ah + (long)bf * NB_ * R_) + t;
    float acc[8] = {0.f, 0.f, 0.f, 0.f, 0.f, 0.f, 0.f, 0.f};
    #pragma unroll 6
    for (int l = 0; l < NB_; l++) {
        uint4 v = fbv[l * (R_ / 8)];
        float a = alpha[s][l];
        float2 p0 = __half22float2(*reinterpret_cast<__half2*>(&v.x));
        float2 p1 = __half22float2(*reinterpret_cast<__half2*>(&v.y));
        float2 p2 = __half22float2(*reinterpret_cast<__half2*>(&v.z));
        float2 p3 = __half22float2(*reinterpret_cast<__half2*>(&v.w));
        acc[0] = fmaf(a, p0.x, acc[0]); acc[1] = fmaf(a, p0.y, acc[1]);
        acc[2] = fmaf(a, p1.x, acc[2]); acc[3] = fmaf(a, p1.y, acc[3]);
        acc[4] = fmaf(a, p2.x, acc[4]); acc[5] = fmaf(a, p2.y, acc[5]);
        acc[6] = fmaf(a, p3.x, acc[6]); acc[7] = fmaf(a, p3.y, acc[7]);
    }
    uint4 o;
    __half2 h0 = __floats2half2_rn(acc[0], acc[1]);
    __half2 h1 = __floats2half2_rn(acc[2], acc[3]);
    __half2 h2 = __floats2half2_rn(acc[4], acc[5]);
    __half2 h3 = __floats2half2_rn(acc[6], acc[7]);
    o.x = *reinterpret_cast<uint32_t*>(&h0);
    o.y = *reinterpret_cast<uint32_t*>(&h1);
    o.z = *reinterpret_cast<uint32_t*>(&h2);
    o.w = *reinterpret_cast<uint32_t*>(&h3);
    reinterpret_cast<uint4*>(g_Fh + (long)bf * D_)[t] = o;
}

// ============================================================================
// K5: e2[b,i,j] = war . tanh(p2[b,i] + p1[b,j] + hp2[b]); p = sum of 4
// K-split partials. grid (32,5)
// ============================================================================
__global__ __launch_bounds__(256) void k5_e2(const float* __restrict__ war)
{
    __shared__ float base[8][H_];
    __shared__ float warr[H_];
    int b = blockIdx.x, i0 = blockIdx.y * 8;
    int tid = threadIdx.x, warp = tid >> 5, lane = tid & 31;
    for (int h = tid; h < H_; h += 256) warr[h] = war[h];
    for (int idx = tid; idx < 8 * H_; idx += 256) {
        int ii = idx >> 9, h = idx & (H_ - 1);
        long o = (long)(b * F_ + i0 + ii) * PM + H_ + h;
        base[ii][h] = (g_p0[o] + g_p1b[o]) + (g_p2b[o] + g_p3b[o])
                    + g_hp2[b * H_ + h];
    }
    __syncthreads();
    for (int jj = 0; jj < 5; jj++) {
        int j = jj * 8 + warp;
        long rowo = (long)(b * F_ + j) * PM;
        float p1v[16];
        #pragma unroll
        for (int kk = 0; kk < 16; kk++) {
            long o = rowo + lane + kk * 32;
            p1v[kk] = (g_p0[o] + g_p1b[o]) + (g_p2b[o] + g_p3b[o]);
        }
        #pragma unroll
        for (int ii = 0; ii < 8; ii++) {
            float part = 0.f;
            #pragma unroll
            for (int kk = 0; kk < 16; kk++) {
                int h = lane + kk * 32;
                part += warr[h] * tanha(base[ii][h] + p1v[kk]);
            }
            #pragma unroll
            for (int off = 16; off; off >>= 1)
                part += __shfl_xor_sync(0xffffffffu, part, off);
            if (lane == 0) g_e2[(long)b * (F_ * F_) + (i0 + ii) * F_ + j] = part;
        }
    }
}

// ============================================================================
// K6: per-batch softmax over F*F, marginals, weighted sums from fp16 feat.
// grid (32,3).
// ============================================================================
__global__ __launch_bounds__(256) void k6_final(float* __restrict__ out)
{
    __shared__ float ex[F_ * F_];
    __shared__ float red[256];
    __shared__ float rowsum[F_], colsum[F_];
    int b = blockIdx.x, tid = threadIdx.x;
    const float* e = g_e2 + b * (F_ * F_);

    float m = -1e30f;
    for (int t = tid; t < F_ * F_; t += 256) m = fmaxf(m, e[t]);
    red[tid] = m; __syncthreads();
    for (int s = 128; s > 0; s >>= 1) {
        if (tid < s) red[tid] = fmaxf(red[tid], red[tid + s]);
        __syncthreads();
    }
    m = red[0]; __syncthreads();

    float sum = 0.f;
    for (int t = tid; t < F_ * F_; t += 256) { float v = expf(e[t] - m); ex[t] = v; sum += v; }
    red[tid] = sum; __syncthreads();
    for (int s = 128; s > 0; s >>= 1) {
        if (tid < s) red[tid] += red[tid + s];
        __syncthreads();
    }
    float inv = 1.f / red[0];

    if (tid < F_) { rowsum[tid] = 0.f; colsum[tid] = 0.f; }
    __syncthreads();
    for (int t = tid; t < F_ * F_; t += 256) {
        float a = ex[t] * inv;
        atomicAdd(&rowsum[t / F_], a);
        atomicAdd(&colsum[t % F_], a);
    }
    __syncthreads();

    int c0 = blockIdx.y * 512;
    for (int d = c0 + tid; d < c0 + 512; d += 256) {
        float r1 = 0.f, r2 = 0.f;
        #pragma unroll 8
        for (int q = 0; q < F_; q++) {
            float fv = __half2float(g_Fh[(long)(b * F_ + q) * D_ + d]);
            r1 = fmaf(colsum[q], fv, r1);
            r2 = fmaf(rowsum[q], fv, r2);
        }
        out[b * (2 * D_) + d]      = r1;
        out[b * (2 * D_) + D_ + d] = r2;
    }
}

// ============================================================================
extern "C" void kernel_launch(void* const* d_in, const int* in_sizes, int n_in,
                              void* d_out, int out_size)
{
    const float* i3d    = (const float*)d_in[0];
    const float* obj    = (const float*)d_in[1];
    const float* hidden = (const float*)d_in[2];
    const float* Wsf    = (const float*)d_in[3];
    const float* bsf    = (const float*)d_in[4];
    const float* Wsh    = (const float*)d_in[5];
    const float* bsh    = (const float*)d_in[6];
    const float* was    = (const float*)d_in[7];
    const float* Wrf    = (const float*)d_in[8];
    const float* brf    = (const float*)d_in[9];
    const float* Wrh    = (const float*)d_in[10];
    const float* brh    = (const float*)d_in[11];
    const float* war    = (const float*)d_in[12];
    float* out = (float*)d_out;

    static cudaStream_t s2 = nullptr;
    static cudaEvent_t ev1 = nullptr, ev2 = nullptr;
    if (s2 == nullptr) {
        cudaStreamCreateWithFlags(&s2, cudaStreamNonBlocking);
        cudaEventCreateWithFlags(&ev1, cudaEventDisableTiming);
        cudaEventCreateWithFlags(&ev2, cudaEventDisableTiming);
    }

    // kmma1: stage-1. kmma2b: i3d part of p (K-chunks 8..23, partials 0/1).
    // kmma2a: obj_att part of p (K-chunks 0..7, partials 2/3).
    auto km1  = kmma<512, 8, 1, 128, 128, 3, 0, 0>;
    auto km2b = kmma<1536, 8, 2, 128, 128, 3, 8, 0>;
    auto km2a = kmma<1536, 4, 2, 128, 128, 3, 0, 2>;
    cudaFuncSetAttribute((const void*)km1,
        cudaFuncAttributeMaxDynamicSharedMemorySize, KCfg<128, 128, 3>::TOT);
    cudaFuncSetAttribute((const void*)km2b,
        cudaFuncAttributeMaxDynamicSharedMemorySize, KCfg<128, 128, 3>::TOT);
    cudaFuncSetAttribute((const void*)km2a,
        cudaFuncAttributeMaxDynamicSharedMemorySize, KCfg<128, 128, 3>::TOT);

    kprep <<<26624, 256>>>(hidden, Wsh, bsh, bsf, Wrh, brh, brf, obj, Wsf, Wrf, i3d);

    // Fork: i3d GEMM runs on s2 concurrently with stage-1 on the main stream.
    cudaEventRecord(ev1, 0);
    cudaStreamWaitEvent(s2, ev1, 0);
    km2b <<<dim3(NBF / 128, 8, 2), 256, KCfg<128, 128, 3>::TOT, s2>>>(nullptr);
    cudaEventRecord(ev2, s2);

    km1 <<<dim3(M1 / 128, 4), 256, KCfg<128, 128, 3>::TOT>>>(was);
    k3_soft <<<NBF / 4, 256>>>();
    km2a <<<dim3(NBF / 128, 8, 2), 256, KCfg<128, 128, 3>::TOT>>>(nullptr);

    // Join: k5 needs all four partial buffers.
    cudaStreamWaitEvent(0, ev2, 0);
    k5_e2   <<<dim3(B_, 5), 256>>>(war);
    k6_final<<<dim3(B_, 3), 256>>>(out);
}